// round 13
// baseline (speedup 1.0000x reference)
#include <cuda_runtime.h>
#include <math.h>

// Fixed problem shape: B=8, N=48, D=2
#define BB 8
#define NN 48
#define MM 2304               // NN*NN candidate pair-vectors per batch
#define T 256                 // threads per block (1 block per batch)
#define CH 9                  // elements per thread (MM / T exactly)
#define KM 10                 // Fourier harmonics of |cos|
#define NQ (2 * KM + 1)       // reduction quantities: C1..C10, S1..S10, count

// Finale packing (single word, integer adds -> deterministic):
//   [60:64) block count, [26:60) S*2^8 (34 bits), [0:26) sum K^2 (26 bits)
__device__ unsigned long long g_pack = 0ULL;

__global__ __launch_bounds__(T, 1)
void fused_kernel(const float* __restrict__ gt,
                  const float* __restrict__ cs,
                  const float* __restrict__ thr,
                  float* __restrict__ out) {
    const int b    = blockIdx.x;
    const int tid  = threadIdx.x;
    const int lane = tid & 31;
    const int wid  = tid >> 5;

    __shared__ float2 sg[NN];
    __shared__ float  wred[8][NQ];
    __shared__ float  fin[NQ];

    if (tid < NN) sg[tid] = ((const float2*)gt)[b * NN + tid];

    // Prefetch all 9 similarity values (MLP=9, one memory round trip)
    float sv[CH];
#pragma unroll
    for (int k = 0; k < CH; k++) sv[k] = cs[b * MM + k * T + tid];
    const float t = thr[0];
    __syncthreads();

    // ---- element phase: harmonic accumulation, no atomics ----
    float C[KM], S[KM], cntf = 0.f;
#pragma unroll
    for (int h = 0; h < KM; h++) { C[h] = 0.f; S[h] = 0.f; }

#pragma unroll
    for (int k = 0; k < CH; k++) {
        float ss = sv[k];
        if (ss >= t) {                      // ref: where(cos < thr, 0, cos)
            int idx = k * T + tid;
            int i = idx / NN;
            int j = idx - i * NN;
            float vx = (sg[i].x - sg[j].x) * ss;
            float vy = (sg[i].y - sg[j].y) * ss;
            if (vx != 0.f || vy != 0.f) {
                // per-element eps as in reference: sqrt(vx^2+eps + vy^2+eps)
                float inv = rsqrtf(vx * vx + 1e-9f + vy * vy + 1e-9f);
                float ux = vx * inv, uy = vy * inv;
                // double angle: cos2t, sin2t (pi-fold unnecessary: 2k*theta invariant)
                float c1 = ux * ux - uy * uy;
                float s1 = 2.f * ux * uy;
                float ck = c1, sk = s1;
                C[0] += ck; S[0] += sk; cntf += 1.f;
#pragma unroll
                for (int h = 1; h < KM; h++) {   // Chebyshev recurrence e^(i2kt)
                    float cn = ck * c1 - sk * s1;
                    float sn = sk * c1 + ck * s1;
                    ck = cn; sk = sn;
                    C[h] += ck; S[h] += sk;
                }
            }
        }
    }

    // ---- warp reduction of all 21 quantities (fixed order -> deterministic)
#pragma unroll
    for (int h = 0; h < KM; h++) {
#pragma unroll
        for (int d = 16; d > 0; d >>= 1) {
            C[h] += __shfl_xor_sync(0xffffffffu, C[h], d);
            S[h] += __shfl_xor_sync(0xffffffffu, S[h], d);
        }
    }
#pragma unroll
    for (int d = 16; d > 0; d >>= 1) cntf += __shfl_xor_sync(0xffffffffu, cntf, d);

    if (lane == 0) {
#pragma unroll
        for (int h = 0; h < KM; h++) { wred[wid][h] = C[h]; wred[wid][KM + h] = S[h]; }
        wred[wid][2 * KM] = cntf;
    }
    __syncthreads();

    // ---- cross-warp: 21 lanes each sum 8 warp partials (fixed order) ----
    if (tid < NQ) {
        float v = 0.f;
#pragma unroll
        for (int w = 0; w < 8; w++) v += wred[w][tid];
        fin[tid] = v;
    }
    __syncthreads();

    // ---- finale: S = (2/pi)K^2 + sum_k a_k (C_k^2 + S_k^2) ----
    if (tid == 0) {
        double Kf = (double)fin[2 * KM];
        long long Ki = (long long)(Kf + 0.5);
        double Ssum = (2.0 / 3.14159265358979323846) * Kf * Kf;
#pragma unroll
        for (int h = 0; h < KM; h++) {
            int k = h + 1;
            double R2 = (double)fin[h] * (double)fin[h]
                      + (double)fin[KM + h] * (double)fin[KM + h];
            double a = (4.0 / 3.14159265358979323846) / (double)(4 * k * k - 1);
            Ssum += ((h & 1) == 0 ? a : -a) * R2;
        }
        long long Sfix = (long long)(fmax(Ssum, 0.0) * 256.0 + 0.5);
        unsigned long long val = (1ULL << 60)
                               | ((unsigned long long)Sfix << 26)
                               | (unsigned long long)(Ki * Ki);
        unsigned long long old = atomicAdd(&g_pack, val);
        unsigned long long tot = old + val;
        if ((tot >> 60) == (unsigned long long)BB) {
            double Stot = (double)((tot >> 26) & 0x3FFFFFFFFULL) * (1.0 / 256.0);
            double k2   = (double)(tot & 0x3FFFFFFULL);
            out[0] = (float)(Stot / k2);
            atomicExch(&g_pack, 0ULL);   // reset for next graph replay
        }
    }
}

extern "C" void kernel_launch(void* const* d_in, const int* in_sizes, int n_in,
                              void* d_out, int out_size) {
    const float* gt  = (const float*)d_in[0];   // [8,48,2]
    const float* cs  = (const float*)d_in[1];   // [8,48,48]
    const float* thr = (const float*)d_in[2];   // [1]
    float* out = (float*)d_out;

    fused_kernel<<<BB, T>>>(gt, cs, thr, out);
}

// round 14
// speedup vs baseline: 1.2694x; 1.2694x over previous
#include <cuda_runtime.h>
#include <math.h>

// Fixed problem shape: B=8, N=48, D=2
#define BB 8
#define NN 48
#define MM 2304               // NN*NN candidate pair-vectors per batch
#define T 1024                // threads per block (1 block per batch)
#define KM 5                  // Fourier harmonics of |cos|
#define NQ (2 * KM + 1)       // reduction quantities: C1..C5, S1..S5, count
#define NW (T / 32)           // warps per block

// Finale packing (single word, integer adds -> deterministic):
//   [60:64) block count, [26:60) S*2^8 (34 bits), [0:26) sum K^2 (26 bits)
__device__ unsigned long long g_pack = 0ULL;

__global__ __launch_bounds__(T, 1)
void fused_kernel(const float* __restrict__ gt,
                  const float* __restrict__ cs,
                  const float* __restrict__ thr,
                  float* __restrict__ out) {
    const int b    = blockIdx.x;
    const int tid  = threadIdx.x;
    const int lane = tid & 31;
    const int wid  = tid >> 5;

    __shared__ float2 sg[NN];
    __shared__ float  wred[NW][NQ];
    __shared__ float  fin[NQ];

    if (tid < NN) sg[tid] = ((const float2*)gt)[b * NN + tid];

    // Prefetch similarity values: 2 full chunks + quarter chunk (MLP=3)
    float s0 = cs[b * MM + tid];
    float s1 = cs[b * MM + T + tid];
    float s2 = (tid < MM - 2 * T) ? cs[b * MM + 2 * T + tid] : -1e30f;
    const float t = thr[0];
    __syncthreads();

    // ---- element phase: harmonic accumulation (no atomics, no atan) ----
    // |cos dth| = 2/pi + (4/pi) sum_k (-1)^(k+1) cos(2k dth)/(4k^2-1)
    // sum_{m,n} cos(2k(th_m-th_n)) = C_k^2 + S_k^2 with phasor sums C_k,S_k.
    float C[KM], S[KM], cntf = 0.f;
#pragma unroll
    for (int h = 0; h < KM; h++) { C[h] = 0.f; S[h] = 0.f; }

    float sv[3] = {s0, s1, s2};
#pragma unroll
    for (int k = 0; k < 3; k++) {
        float ss = sv[k];
        bool valid = (k < 2) || (tid < MM - 2 * T);
        if (valid && ss >= t) {             // ref: where(cos < thr, 0, cos)
            int idx = k * T + tid;
            int i = idx / NN;
            int j = idx - i * NN;
            float vx = (sg[i].x - sg[j].x) * ss;
            float vy = (sg[i].y - sg[j].y) * ss;
            if (vx != 0.f || vy != 0.f) {
                // per-element eps as in reference: sqrt(vx^2+eps + vy^2+eps)
                float inv2 = 1.0f / (vx * vx + 1e-9f + vy * vy + 1e-9f);
                // double angle of the unit vector: cos2t, sin2t
                float c1 = (vx * vx - vy * vy) * inv2;
                float s1_ = (2.f * vx * vy) * inv2;
                float ck = c1, sk = s1_;
                C[0] += ck; S[0] += sk; cntf += 1.f;
#pragma unroll
                for (int h = 1; h < KM; h++) {   // Chebyshev recurrence e^(i2kt)
                    float cn = ck * c1 - sk * s1_;
                    float sn = sk * c1 + ck * s1_;
                    ck = cn; sk = sn;
                    C[h] += ck; S[h] += sk;
                }
            }
        }
    }

    // ---- warp reduction of 11 quantities (fixed order -> deterministic) ----
#pragma unroll
    for (int h = 0; h < KM; h++) {
#pragma unroll
        for (int d = 16; d > 0; d >>= 1) {
            C[h] += __shfl_xor_sync(0xffffffffu, C[h], d);
            S[h] += __shfl_xor_sync(0xffffffffu, S[h], d);
        }
    }
#pragma unroll
    for (int d = 16; d > 0; d >>= 1) cntf += __shfl_xor_sync(0xffffffffu, cntf, d);

    if (lane == 0) {
#pragma unroll
        for (int h = 0; h < KM; h++) { wred[wid][h] = C[h]; wred[wid][KM + h] = S[h]; }
        wred[wid][2 * KM] = cntf;
    }
    __syncthreads();

    // ---- cross-warp: 11 lanes each sum NW warp partials (fixed order) ----
    if (tid < NQ) {
        float v = 0.f;
#pragma unroll
        for (int w = 0; w < NW; w++) v += wred[w][tid];
        fin[tid] = v;
    }
    __syncthreads();

    // ---- per-block finale in float (fixed order -> deterministic) ----
    if (tid == 0) {
        float Kf = fin[2 * KM];
        long long Ki = (long long)(Kf + 0.5f);
        float Ssum = 0.63661977236758f * Kf * Kf;   // 2/pi * K^2
#pragma unroll
        for (int h = 0; h < KM; h++) {
            int k = h + 1;
            float R2 = fin[h] * fin[h] + fin[KM + h] * fin[KM + h];
            float a = 1.27323954473516f / (float)(4 * k * k - 1);  // 4/pi/(4k^2-1)
            Ssum += ((h & 1) == 0 ? a : -a) * R2;
        }
        long long Sfix = (long long)(fmaxf(Ssum, 0.f) * 256.f + 0.5f);
        unsigned long long val = (1ULL << 60)
                               | ((unsigned long long)Sfix << 26)
                               | (unsigned long long)(Ki * Ki);
        unsigned long long old = atomicAdd(&g_pack, val);
        unsigned long long tot = old + val;
        if ((tot >> 60) == (unsigned long long)BB) {
            float Stot = (float)((tot >> 26) & 0x3FFFFFFFFULL) * (1.0f / 256.0f);
            float k2   = (float)(tot & 0x3FFFFFFULL);
            out[0] = Stot / k2;
            atomicExch(&g_pack, 0ULL);   // reset for next graph replay
        }
    }
}

extern "C" void kernel_launch(void* const* d_in, const int* in_sizes, int n_in,
                              void* d_out, int out_size) {
    const float* gt  = (const float*)d_in[0];   // [8,48,2]
    const float* cs  = (const float*)d_in[1];   // [8,48,48]
    const float* thr = (const float*)d_in[2];   // [1]
    float* out = (float*)d_out;

    fused_kernel<<<BB, T>>>(gt, cs, thr, out);
}

// round 16
// speedup vs baseline: 1.6618x; 1.3092x over previous
#include <cuda_runtime.h>
#include <math.h>

// Fixed problem shape: B=8, N=48, D=2
#define BB 8
#define NN 48
#define MM 2304               // NN*NN candidate pair-vectors per batch
#define T 512                 // threads per block (1 block per batch)
#define NW (T / 32)           // 16 warps
#define KM 3                  // Fourier harmonics of |cos|
#define NQ (2 * KM + 1)       // C1..C3, S1..S3, count

// Finale packing (single word, integer adds -> deterministic):
//   [60:64) block count, [26:60) S*2^8 (34 bits), [0:26) sum K^2 (26 bits)
__device__ unsigned long long g_pack = 0ULL;

__global__ __launch_bounds__(T, 1)
void fused_kernel(const float* __restrict__ gt,
                  const float* __restrict__ cs,
                  const float* __restrict__ thr,
                  float* __restrict__ out) {
    const int b    = blockIdx.x;
    const int tid  = threadIdx.x;
    const int lane = tid & 31;
    const int wid  = tid >> 5;

    __shared__ float2 sg[NN];
    __shared__ float  wred[NQ][NW];   // transposed: contiguous per quantity
    __shared__ float  fin[NQ];

    if (tid < NN) sg[tid] = ((const float2*)gt)[b * NN + tid];

    // Prefetch similarity values: 4 full chunks + half chunk (MLP=5)
    float sv[5];
#pragma unroll
    for (int k = 0; k < 4; k++) sv[k] = cs[b * MM + k * T + tid];
    sv[4] = (tid < MM - 4 * T) ? cs[b * MM + 4 * T + tid] : -1e30f;
    const float t = thr[0];
    __syncthreads();

    // ---- element phase: harmonic accumulation (no atomics, no atan) ----
    // |cos dth| = 2/pi + (4/pi) sum_k (-1)^(k+1) cos(2k dth)/(4k^2-1)
    // sum_{m,n} cos(2k(th_m-th_n)) = C_k^2 + S_k^2 with phasor sums C_k, S_k.
    float C[KM], S[KM];
    int cnt = 0;
#pragma unroll
    for (int h = 0; h < KM; h++) { C[h] = 0.f; S[h] = 0.f; }

#pragma unroll
    for (int k = 0; k < 5; k++) {
        float ss = sv[k];
        bool valid = (k < 4) || (tid < MM - 4 * T);
        int f = 0;
        if (valid && ss >= t) {             // ref: where(cos < thr, 0, cos)
            int idx = k * T + tid;
            int i = idx / NN;
            int j = idx - i * NN;
            float vx = (sg[i].x - sg[j].x) * ss;
            float vy = (sg[i].y - sg[j].y) * ss;
            if (vx != 0.f || vy != 0.f) {
                f = 1;
                // per-element eps as in reference: sqrt(vx^2+eps + vy^2+eps)
                float inv2 = 1.0f / (vx * vx + 1e-9f + vy * vy + 1e-9f);
                // double angle of the unit vector: cos2t, sin2t
                float c1 = (vx * vx - vy * vy) * inv2;
                float s1 = (2.f * vx * vy) * inv2;
                C[0] += c1; S[0] += s1;
                float c2 = c1 * c1 - s1 * s1;       // e^(i4t)
                float s2 = 2.f * s1 * c1;
                C[1] += c2; S[1] += s2;
                float c3 = c2 * c1 - s2 * s1;       // e^(i6t)
                float s3 = s2 * c1 + c2 * s1;
                C[2] += c3; S[2] += s3;
            }
        }
        // warp-uniform count: every lane sees the same ballot
        cnt += __popc(__ballot_sync(0xffffffffu, f));
    }

    // ---- warp reduction of 6 float quantities (fixed order, 30 shfl) ----
#pragma unroll
    for (int h = 0; h < KM; h++) {
#pragma unroll
        for (int d = 16; d > 0; d >>= 1) {
            C[h] += __shfl_xor_sync(0xffffffffu, C[h], d);
            S[h] += __shfl_xor_sync(0xffffffffu, S[h], d);
        }
    }
    if (lane == 0) {
#pragma unroll
        for (int h = 0; h < KM; h++) {
            wred[h][wid]      = C[h];
            wred[KM + h][wid] = S[h];
        }
        wred[2 * KM][wid] = (float)cnt;   // cnt is warp-uniform
    }
    __syncthreads();

    // ---- cross-warp: 7 lanes each sum 16 contiguous partials ----
    if (tid < NQ) {
        const float4* p = (const float4*)wred[tid];
        float4 a = p[0], c = p[1], d2 = p[2], e = p[3];
        float v = ((a.x + a.y) + (a.z + a.w)) + ((c.x + c.y) + (c.z + c.w))
                + ((d2.x + d2.y) + (d2.z + d2.w)) + ((e.x + e.y) + (e.z + e.w));
        fin[tid] = v;
    }
    __syncthreads();

    // ---- per-block finale in float (fixed order -> deterministic) ----
    if (tid == 0) {
        float Kf = fin[2 * KM];
        long long Ki = (long long)(Kf + 0.5f);
        float Ssum = 0.636619772367581f * Kf * Kf;        // 2/pi * K^2
        float R1 = fin[0] * fin[0] + fin[KM + 0] * fin[KM + 0];
        float R2 = fin[1] * fin[1] + fin[KM + 1] * fin[KM + 1];
        float R3 = fin[2] * fin[2] + fin[KM + 2] * fin[KM + 2];
        Ssum += (1.27323954473516f / 3.f)  * R1;          // +4/pi/3
        Ssum -= (1.27323954473516f / 15.f) * R2;          // -4/pi/15
        Ssum += (1.27323954473516f / 35.f) * R3;          // +4/pi/35
        long long Sfix = (long long)(fmaxf(Ssum, 0.f) * 256.f + 0.5f);
        unsigned long long val = (1ULL << 60)
                               | ((unsigned long long)Sfix << 26)
                               | (unsigned long long)(Ki * Ki);
        unsigned long long old = atomicAdd(&g_pack, val);
        unsigned long long tot = old + val;
        if ((tot >> 60) == (unsigned long long)BB) {
            float Stot = (float)((tot >> 26) & 0x3FFFFFFFFULL) * (1.0f / 256.0f);
            float k2   = (float)(tot & 0x3FFFFFFULL);
            out[0] = Stot / k2;
            atomicExch(&g_pack, 0ULL);   // reset for next graph replay
        }
    }
}

extern "C" void kernel_launch(void* const* d_in, const int* in_sizes, int n_in,
                              void* d_out, int out_size) {
    const float* gt  = (const float*)d_in[0];   // [8,48,2]
    const float* cs  = (const float*)d_in[1];   // [8,48,48]
    const float* thr = (const float*)d_in[2];   // [1]
    float* out = (float*)d_out;

    fused_kernel<<<BB, T>>>(gt, cs, thr, out);
}